// round 8
// baseline (speedup 1.0000x reference)
#include <cuda_runtime.h>
#include <cuda_bf16.h>
#include <math.h>

#define BB 8
#define NN 1024
#define HH 128
#define NHD 4
#define DH 32
#define NCOE 50
#define NSC 4

// ---------------- static device scratch (no allocations allowed) ----------------
__device__ __align__(16) float g_eig[BB * NN * HH];                  // 4 MB
__device__ __align__(16) float g_x[BB * NN * HH];                    // 4 MB
__device__ __align__(16) float g_qkv[BB * NN * 3 * HH];              // 12 MB (reused as FFN scratch)
__device__ __align__(16) float g_scores[(size_t)BB * NHD * NN * NN]; // 128 MB
__device__ __align__(16) float g_o[BB * NN * HH];                    // 4 MB
__device__ float g_rowsum[BB * HH];
__device__ float g_csc[BB * NCOE];
__device__ float g_cwv[BB * NCOE];
__device__ float g_cscl[BB * NSC];
__device__ __align__(16) float g_fsa[BB * NN * 8];
__device__ __align__(16) float g_normp[8][5 * BB * NN];
__device__ __align__(16) float g_norm[5 * BB * NN];

// ---------------- 1. sine encoding + eigw linear ----------------
__global__ void k_encode(const float* __restrict__ ev, const float* __restrict__ W,
                         const float* __restrict__ bias) {
    int tok = blockIdx.x;   // b*N+n
    int t = threadIdx.x;    // 0..127
    __shared__ float feat[129];
    float e = ev[tok];
    if (t < 64) {
        float div = expf(-(float)(2 * t) * (9.210340371976184f / 128.0f)); // ln(1e4)/H
        float pe = e * 100.0f * div;
        feat[1 + t] = sinf(pe);
        feat[65 + t] = cosf(pe);
    }
    if (t == 0) feat[0] = e;
    __syncthreads();
    float acc = bias[t];
    const float* w = W + t * 129;
#pragma unroll 4
    for (int j = 0; j < 129; j++) acc = fmaf(w[j], feat[j], acc);
    g_eig[(size_t)tok * HH + t] = acc;
}

// ---------------- layernorm ----------------
__global__ void k_ln(const float* __restrict__ in, float* __restrict__ out,
                     const float* __restrict__ g, const float* __restrict__ b) {
    int tok = blockIdx.x, t = threadIdx.x;
    float x = in[(size_t)tok * HH + t];
    __shared__ float r1[4], r2[4];
    float s = x;
#pragma unroll
    for (int o = 16; o > 0; o >>= 1) s += __shfl_xor_sync(0xffffffffu, s, o);
    if ((t & 31) == 0) r1[t >> 5] = s;
    __syncthreads();
    float mu = (r1[0] + r1[1] + r1[2] + r1[3]) * (1.0f / HH);
    float d = x - mu;
    float v = d * d;
#pragma unroll
    for (int o = 16; o > 0; o >>= 1) v += __shfl_xor_sync(0xffffffffu, v, o);
    if ((t & 31) == 0) r2[t >> 5] = v;
    __syncthreads();
    float var = (r2[0] + r2[1] + r2[2] + r2[3]) * (1.0f / HH);
    out[(size_t)tok * HH + t] = d * rsqrtf(var + 1e-5f) * g[t] + b[t];
}

// ---------------- generic dense: Y[M,O] = act(X[M,128] @ W[O,128]^T + b) (+R) ----------------
// grid (O/64, M/64), block 256, tile 64x64, micro 4x4, ktile 16
template <int ACT, bool RES>
__global__ __launch_bounds__(256) void k_dense(const float* __restrict__ X,
                                               const float* __restrict__ W,
                                               const float* __restrict__ bias,
                                               const float* __restrict__ R,
                                               float* __restrict__ Y, int O) {
    __shared__ float Xs[16][64];
    __shared__ float Ws[16][64];
    int t = threadIdx.x, tx = t & 15, ty = t >> 4;
    int m0 = blockIdx.y * 64, o0 = blockIdx.x * 64;
    float acc[4][4] = {};
    int r = t >> 2, kq = (t & 3) * 4;
    for (int k0 = 0; k0 < HH; k0 += 16) {
        __syncthreads();
        float4 xv = *(const float4*)&X[(size_t)(m0 + r) * HH + k0 + kq];
        Xs[kq + 0][r] = xv.x; Xs[kq + 1][r] = xv.y; Xs[kq + 2][r] = xv.z; Xs[kq + 3][r] = xv.w;
        float4 wv = *(const float4*)&W[(size_t)(o0 + r) * HH + k0 + kq];
        Ws[kq + 0][r] = wv.x; Ws[kq + 1][r] = wv.y; Ws[kq + 2][r] = wv.z; Ws[kq + 3][r] = wv.w;
        __syncthreads();
#pragma unroll
        for (int k = 0; k < 16; k++) {
            float4 a = *(const float4*)&Xs[k][ty * 4];
            float4 bb = *(const float4*)&Ws[k][tx * 4];
            float av[4] = {a.x, a.y, a.z, a.w};
            float bv[4] = {bb.x, bb.y, bb.z, bb.w};
#pragma unroll
            for (int i = 0; i < 4; i++)
#pragma unroll
                for (int j = 0; j < 4; j++) acc[i][j] = fmaf(av[i], bv[j], acc[i][j]);
        }
    }
#pragma unroll
    for (int i = 0; i < 4; i++) {
        int m = m0 + ty * 4 + i;
#pragma unroll
        for (int j = 0; j < 4; j++) {
            int o = o0 + tx * 4 + j;
            float v = acc[i][j] + bias[o];
            if (ACT == 1) v = 0.5f * v * (1.0f + erff(v * 0.70710678118654752f));
            if (RES) v += R[(size_t)m * O + o];
            Y[(size_t)m * O + o] = v;
        }
    }
}

// ---------------- attention: scores = q@k^T/sqrt(dh), masked ----------------
// grid (16 ntile, 16 mtile, 32 bh), block 256
__global__ __launch_bounds__(256) void k_scores(const int* __restrict__ length) {
    int bh = blockIdx.z;
    int b = bh >> 2, h = bh & 3;
    int n0 = blockIdx.y * 64, m0 = blockIdx.x * 64;
    __shared__ float Qs[32][64];
    __shared__ float Ks[32][64];
    int t = threadIdx.x, tx = t & 15, ty = t >> 4;
    {
        int r = t >> 2, kq = (t & 3) * 8;
        const float* qp = &g_qkv[((size_t)b * NN + (n0 + r)) * (3 * HH) + h * DH + kq];
        float4 v0 = *(const float4*)qp, v1 = *(const float4*)(qp + 4);
        Qs[kq + 0][r] = v0.x; Qs[kq + 1][r] = v0.y; Qs[kq + 2][r] = v0.z; Qs[kq + 3][r] = v0.w;
        Qs[kq + 4][r] = v1.x; Qs[kq + 5][r] = v1.y; Qs[kq + 6][r] = v1.z; Qs[kq + 7][r] = v1.w;
        const float* kp = &g_qkv[((size_t)b * NN + (m0 + r)) * (3 * HH) + HH + h * DH + kq];
        float4 k0v = *(const float4*)kp, k1v = *(const float4*)(kp + 4);
        Ks[kq + 0][r] = k0v.x; Ks[kq + 1][r] = k0v.y; Ks[kq + 2][r] = k0v.z; Ks[kq + 3][r] = k0v.w;
        Ks[kq + 4][r] = k1v.x; Ks[kq + 5][r] = k1v.y; Ks[kq + 6][r] = k1v.z; Ks[kq + 7][r] = k1v.w;
    }
    __syncthreads();
    float acc[4][4] = {};
#pragma unroll 8
    for (int k = 0; k < 32; k++) {
        float4 a = *(const float4*)&Qs[k][ty * 4];
        float4 bb = *(const float4*)&Ks[k][tx * 4];
        float av[4] = {a.x, a.y, a.z, a.w};
        float bv[4] = {bb.x, bb.y, bb.z, bb.w};
#pragma unroll
        for (int i = 0; i < 4; i++)
#pragma unroll
            for (int j = 0; j < 4; j++) acc[i][j] = fmaf(av[i], bv[j], acc[i][j]);
    }
    int len = length[b];
    float* S = g_scores + (size_t)bh * NN * NN;
    const float sc = 0.17677669529663688f; // 1/sqrt(32)
    int mb = m0 + tx * 4;
#pragma unroll
    for (int i = 0; i < 4; i++) {
        int n = n0 + ty * 4 + i;
        float4 v;
        v.x = (mb + 0 >= len) ? -1e9f : acc[i][0] * sc;
        v.y = (mb + 1 >= len) ? -1e9f : acc[i][1] * sc;
        v.z = (mb + 2 >= len) ? -1e9f : acc[i][2] * sc;
        v.w = (mb + 3 >= len) ? -1e9f : acc[i][3] * sc;
        *(float4*)&S[(size_t)n * NN + mb] = v;
    }
}

// ---------------- softmax over rows of 1024 ----------------
__global__ __launch_bounds__(256) void k_softmax() {
    size_t row = blockIdx.x;
    float4* p = (float4*)(g_scores + row * NN);
    int t = threadIdx.x;
    float4 v = p[t];
    __shared__ float redm[8], reds[8];
    float mx = fmaxf(fmaxf(v.x, v.y), fmaxf(v.z, v.w));
#pragma unroll
    for (int o = 16; o > 0; o >>= 1) mx = fmaxf(mx, __shfl_xor_sync(0xffffffffu, mx, o));
    if ((t & 31) == 0) redm[t >> 5] = mx;
    __syncthreads();
    mx = redm[0];
#pragma unroll
    for (int i = 1; i < 8; i++) mx = fmaxf(mx, redm[i]);
    v.x = __expf(v.x - mx); v.y = __expf(v.y - mx);
    v.z = __expf(v.z - mx); v.w = __expf(v.w - mx);
    float s = v.x + v.y + v.z + v.w;
#pragma unroll
    for (int o = 16; o > 0; o >>= 1) s += __shfl_xor_sync(0xffffffffu, s, o);
    if ((t & 31) == 0) reds[t >> 5] = s;
    __syncthreads();
    s = reds[0] + reds[1] + reds[2] + reds[3] + reds[4] + reds[5] + reds[6] + reds[7];
    float inv = 1.0f / s;
    v.x *= inv; v.y *= inv; v.z *= inv; v.w *= inv;
    p[t] = v;
}

// ---------------- O = attn @ v ----------------
// grid (16 ntiles, 32 bh), block 256; tile 64n x 32d
__global__ __launch_bounds__(256) void k_av() {
    int bh = blockIdx.y;
    int b = bh >> 2, h = bh & 3;
    int n0 = blockIdx.x * 64;
    __shared__ float Ss[32][64];
    __shared__ float Vs[32][32];
    int t = threadIdx.x, tx = t & 15, ty = t >> 4;
    const float* S = g_scores + (size_t)bh * NN * NN;
    float acc[4][2] = {};
    for (int k0 = 0; k0 < NN; k0 += 32) {
        __syncthreads();
        {
            int r = t >> 2, kq = (t & 3) * 8;
            const float* sp = &S[(size_t)(n0 + r) * NN + k0 + kq];
            float4 s0 = *(const float4*)sp, s1 = *(const float4*)(sp + 4);
            Ss[kq + 0][r] = s0.x; Ss[kq + 1][r] = s0.y; Ss[kq + 2][r] = s0.z; Ss[kq + 3][r] = s0.w;
            Ss[kq + 4][r] = s1.x; Ss[kq + 5][r] = s1.y; Ss[kq + 6][r] = s1.z; Ss[kq + 7][r] = s1.w;
        }
        if (t < 128) {
            int r = t >> 2, kq = (t & 3) * 8;
            const float* vp = &g_qkv[((size_t)b * NN + (k0 + r)) * (3 * HH) + 2 * HH + h * DH + kq];
            float4 v0 = *(const float4*)vp, v1 = *(const float4*)(vp + 4);
            *(float4*)&Vs[r][kq] = v0;
            *(float4*)&Vs[r][kq + 4] = v1;
        }
        __syncthreads();
#pragma unroll 8
        for (int k = 0; k < 32; k++) {
            float4 sn = *(const float4*)&Ss[k][ty * 4];
            float va = Vs[k][tx * 2], vb = Vs[k][tx * 2 + 1];
            float sv[4] = {sn.x, sn.y, sn.z, sn.w};
#pragma unroll
            for (int i = 0; i < 4; i++) {
                acc[i][0] = fmaf(sv[i], va, acc[i][0]);
                acc[i][1] = fmaf(sv[i], vb, acc[i][1]);
            }
        }
    }
#pragma unroll
    for (int i = 0; i < 4; i++) {
        size_t base = ((size_t)b * NN + (n0 + ty * 4 + i)) * HH + h * DH + tx * 2;
        g_o[base] = acc[i][0];
        g_o[base + 1] = acc[i][1];
    }
}

// ---------------- masked row-sum pool ----------------
__global__ void k_rowsum(const int* __restrict__ length) {
    int b = blockIdx.x, t = threadIdx.x; // 512 threads
    int h = t & 127, part = t >> 7;
    int len = length[b];
    float s = 0.0f;
    for (int n = part; n < len; n += 4) s += g_eig[(size_t)(b * NN + n) * HH + h];
    __shared__ float sm[512];
    sm[t] = s;
    __syncthreads();
    if (part == 0) g_rowsum[b * HH + h] = sm[h] + sm[128 + h] + sm[256 + h] + sm[384 + h];
}

// ---------------- decoders: pooled linears + sigmoid + normalize ----------------
__global__ void k_decode(const int* __restrict__ length,
                         const float* __restrict__ dscW, const float* __restrict__ dscB,
                         const float* __restrict__ dwavW, const float* __restrict__ dwavB,
                         const float* __restrict__ dsclW, const float* __restrict__ dsclB) {
    int b = blockIdx.x, t = threadIdx.x; // 128 threads
    __shared__ float rs[HH];
    __shared__ float s1[NCOE], s2[NCOE];
    __shared__ float sums[2];
    rs[t] = g_rowsum[b * HH + t];
    __syncthreads();
    float lenf = (float)length[b];
    float inv = 1.0f / (lenf + 1e-8f);
    float cs = 0.0f, cw = 0.0f;
    if (t < NCOE) {
        float a = dscB[t] * lenf, a2 = dwavB[t] * lenf;
        const float* w1 = dscW + t * HH;
        const float* w2 = dwavW + t * HH;
        for (int k = 0; k < HH; k++) {
            a = fmaf(rs[k], w1[k], a);
            a2 = fmaf(rs[k], w2[k], a2);
        }
        cs = 1.0f / (1.0f + expf(-a * inv));
        cw = 1.0f / (1.0f + expf(-a2 * inv));
        s1[t] = cs; s2[t] = cw;
    }
    if (t < NSC) {
        float a = dsclB[t] * lenf;
        const float* w = dsclW + t * HH;
        for (int k = 0; k < HH; k++) a = fmaf(rs[k], w[k], a);
        g_cscl[b * NSC + t] = 5.0f / (1.0f + expf(-a * inv));
    }
    __syncthreads();
    if (t == 0) {
        float x = 0.0f, y = 0.0f;
        for (int i = 0; i < NCOE; i++) { x += s1[i]; y += s2[i]; }
        sums[0] = x; sums[1] = y;
    }
    __syncthreads();
    if (t < NCOE) {
        g_csc[b * NCOE + t] = cs / (sums[0] + 1e-8f);
        g_cwv[b * NCOE + t] = cw / (sums[1] + 1e-8f);
    }
}

// ---------------- Chebyshev recurrences -> normalized fsa [B,N,5] (stride 8) ----------------
__global__ void k_fsa(const float* __restrict__ ev) {
    int b = blockIdx.y;
    int n = blockIdx.x * 256 + threadIdx.x;
    __shared__ float csc[NCOE], cwv[NCOE], scl[NSC];
    int t = threadIdx.x;
    if (t < NCOE) { csc[t] = g_csc[b * NCOE + t]; cwv[t] = g_cwv[b * NCOE + t]; }
    if (t < NSC) scl[t] = g_cscl[b * NSC + t];
    __syncthreads();
    float e = ev[b * NN + n];
    float f[5];
    {
        // scal series: to0=y, then odds of the scan
        float y = e - 1.0f;
        float te = 1.0f, to = y;
        float a = csc[0] * (0.5f * (1.0f - to));
        for (int c = 1; c < NCOE; c++) {
            te = 2.0f * y * to - te;
            to = 2.0f * y * te - to;
            a = fmaf(csc[c], 0.5f * (1.0f - to), a);
        }
        f[0] = a;
    }
#pragma unroll
    for (int s = 0; s < NSC; s++) {
        // wav series: te0=1, then evens of the scan
        float fw = e * scl[s];
        if (fw > 2.0f) fw = 0.0f;
        float y = fw - 1.0f;
        float te = 1.0f, to = y;
        float a = cwv[0] * (0.5f * (1.0f - te));
        for (int c = 1; c < NCOE; c++) {
            te = 2.0f * y * to - te;
            to = 2.0f * y * te - to;
            a = fmaf(cwv[c], 0.5f * (1.0f - te), a);
        }
        f[1 + s] = a;
    }
    float nr = sqrtf(f[0] * f[0] + f[1] * f[1] + f[2] * f[2] + f[3] * f[3] + f[4] * f[4]);
    float invn = 1.0f / (nr + 1e-8f);
    float* outp = &g_fsa[(size_t)(b * NN + n) * 8];
#pragma unroll
    for (int s = 0; s < 5; s++) outp[s] = f[s] * invn;
    outp[5] = 0.0f; outp[6] = 0.0f; outp[7] = 0.0f;
}

// ---------------- big symmetric 5-scale filter GEMM (writes unnormalized filters) ----------------
// grid (136 tile-pairs ti<=tj, B), block 256; tile 64x64, micro 4x4, ktile 16, 5 scales fused
__global__ __launch_bounds__(256) void k_filters(const float* __restrict__ evc,
                                                 float* __restrict__ out) {
    int b = blockIdx.y;
    int idx = blockIdx.x;
    int ti = 0, rem = idx;
    while (rem >= 16 - ti) { rem -= 16 - ti; ti++; }
    int tj = ti + rem;
    const float* A = evc + (size_t)b * NN * NN;
    __shared__ float As[5][16][64];
    __shared__ float Bs[16][64];
    int t = threadIdx.x, tx = t & 15, ty = t >> 4;
    int n0 = ti * 64, m0 = tj * 64;
    float acc[5][4][4] = {};
    int r = t >> 2, kq = (t & 3) * 4;
    const float* fs = g_fsa + (size_t)b * NN * 8;
    for (int k0 = 0; k0 < NN; k0 += 16) {
        __syncthreads();
        {
            float4 bv = *(const float4*)&A[(size_t)(m0 + r) * NN + k0 + kq];
            Bs[kq + 0][r] = bv.x; Bs[kq + 1][r] = bv.y; Bs[kq + 2][r] = bv.z; Bs[kq + 3][r] = bv.w;
            float4 av = *(const float4*)&A[(size_t)(n0 + r) * NN + k0 + kq];
            float a4[4] = {av.x, av.y, av.z, av.w};
#pragma unroll
            for (int kk = 0; kk < 4; kk++) {
                int k = k0 + kq + kk;
                float4 w4 = *(const float4*)&fs[(size_t)k * 8];
                float w5 = fs[(size_t)k * 8 + 4];
                As[0][kq + kk][r] = a4[kk] * w4.x;
                As[1][kq + kk][r] = a4[kk] * w4.y;
                As[2][kq + kk][r] = a4[kk] * w4.z;
                As[3][kq + kk][r] = a4[kk] * w4.w;
                As[4][kq + kk][r] = a4[kk] * w5;
            }
        }
        __syncthreads();
#pragma unroll 4
        for (int k = 0; k < 16; k++) {
            float4 bm = *(const float4*)&Bs[k][tx * 4];
            float bmv[4] = {bm.x, bm.y, bm.z, bm.w};
#pragma unroll
            for (int s = 0; s < 5; s++) {
                float4 an = *(const float4*)&As[s][k][ty * 4];
                float anv[4] = {an.x, an.y, an.z, an.w};
#pragma unroll
                for (int i = 0; i < 4; i++)
#pragma unroll
                    for (int j = 0; j < 4; j++)
                        acc[s][i][j] = fmaf(anv[i], bmv[j], acc[s][i][j]);
            }
        }
    }
    const size_t PLANE = (size_t)NN * NN;
#pragma unroll
    for (int s = 0; s < 5; s++) {
        float* base = out + ((size_t)s * BB + b) * PLANE;
#pragma unroll
        for (int i = 0; i < 4; i++) {
            int n = n0 + ty * 4 + i;
            float4 v = make_float4(acc[s][i][0], acc[s][i][1], acc[s][i][2], acc[s][i][3]);
            *(float4*)&base[(size_t)n * NN + m0 + tx * 4] = v;
        }
        if (ti != tj) {
#pragma unroll
            for (int i = 0; i < 4; i++)
#pragma unroll
                for (int j = 0; j < 4; j++)
                    base[(size_t)(m0 + tx * 4 + j) * NN + (n0 + ty * 4 + i)] = acc[s][i][j];
        }
    }
}

// ---------------- column norms (over n) in two phases, then divide ----------------
__global__ void k_normp(const float* __restrict__ out) {
    int m = blockIdx.x * 256 + threadIdx.x;
    int sb = blockIdx.y;  // s*B+b, 0..39
    int np = blockIdx.z;  // 0..7
    const float* base = out + (size_t)sb * NN * NN;
    float a = 0.0f;
    int nEnd = np * 128 + 128;
    for (int n = np * 128; n < nEnd; n++) {
        float v = base[(size_t)n * NN + m];
        a = fmaf(v, v, a);
    }
    g_normp[np][sb * NN + m] = a;
}

__global__ void k_normc() {
    int i = blockIdx.x * 256 + threadIdx.x; // < 40960
    float a = 0.0f;
#pragma unroll
    for (int p = 0; p < 8; p++) a += g_normp[p][i];
    g_norm[i] = fmaxf(sqrtf(a), 1e-12f);
}

__global__ void k_div(float* __restrict__ out) {
    size_t i = (size_t)blockIdx.x * 256 + threadIdx.x; // float4 index
    size_t gidx = i * 4;
    int sb = (int)(gidx >> 20);        // plane of N*N = 1<<20 elements
    int m = (int)(gidx & (NN - 1));
    float4 v = ((float4*)out)[i];
    float4 nv = *(const float4*)&g_norm[sb * NN + m];
    v.x /= nv.x; v.y /= nv.y; v.z /= nv.z; v.w /= nv.w;
    ((float4*)out)[i] = v;
}

// ---------------- launch ----------------
extern "C" void kernel_launch(void* const* d_in, const int* in_sizes, int n_in,
                              void* d_out, int out_size) {
    const float* eigenvalue = (const float*)d_in[0];
    const float* eigenvector = (const float*)d_in[1];
    const float* eigw_W = (const float*)d_in[2];
    const float* eigw_b = (const float*)d_in[3];
    const float* ln1_g = (const float*)d_in[4];
    const float* ln1_b = (const float*)d_in[5];
    const float* qkv_W = (const float*)d_in[6];
    const float* qkv_b = (const float*)d_in[7];
    const float* out_W = (const float*)d_in[8];
    const float* out_b = (const float*)d_in[9];
    const float* ln2_g = (const float*)d_in[10];
    const float* ln2_b = (const float*)d_in[11];
    const float* ffn1_W = (const float*)d_in[12];
    const float* ffn1_b = (const float*)d_in[13];
    const float* ffn2_W = (const float*)d_in[14];
    const float* ffn2_b = (const float*)d_in[15];
    const float* dsc_W = (const float*)d_in[16];
    const float* dsc_b = (const float*)d_in[17];
    const float* dwav_W = (const float*)d_in[18];
    const float* dwav_b = (const float*)d_in[19];
    const float* dscl_W = (const float*)d_in[20];
    const float* dscl_b = (const float*)d_in[21];
    const int* length = (const int*)d_in[22];
    float* outp = (float*)d_out;

    float *p_eig, *p_x, *p_qkv, *p_o;
    cudaGetSymbolAddress((void**)&p_eig, g_eig);
    cudaGetSymbolAddress((void**)&p_x, g_x);
    cudaGetSymbolAddress((void**)&p_qkv, g_qkv);
    cudaGetSymbolAddress((void**)&p_o, g_o);

    // encoder
    k_encode<<<BB * NN, HH>>>(eigenvalue, eigw_W, eigw_b);
    // MHA block
    k_ln<<<BB * NN, HH>>>(p_eig, p_x, ln1_g, ln1_b);
    k_dense<0, false><<<dim3(6, 128), 256>>>(p_x, qkv_W, qkv_b, nullptr, p_qkv, 3 * HH);
    k_scores<<<dim3(16, 16, BB * NHD), 256>>>(length);
    k_softmax<<<BB * NHD * NN, 256>>>();
    k_av<<<dim3(16, BB * NHD), 256>>>();
    k_dense<0, true><<<dim3(2, 128), 256>>>(p_o, out_W, out_b, p_eig, p_eig, HH);
    // FFN block
    k_ln<<<BB * NN, HH>>>(p_eig, p_x, ln2_g, ln2_b);
    k_dense<1, false><<<dim3(2, 128), 256>>>(p_x, ffn1_W, ffn1_b, nullptr, p_qkv, HH);
    k_dense<0, true><<<dim3(2, 128), 256>>>(p_qkv, ffn2_W, ffn2_b, p_eig, p_eig, HH);
    // decoders
    k_rowsum<<<BB, 512>>>(length);
    k_decode<<<BB, 128>>>(length, dsc_W, dsc_b, dwav_W, dwav_b, dscl_W, dscl_b);
    // spectral filters
    k_fsa<<<dim3(4, BB), 256>>>(eigenvalue);
    k_filters<<<dim3(136, BB), 256>>>(eigenvector, outp);
    // normalize columns
    k_normp<<<dim3(4, 5 * BB, 8), 256>>>(outp);
    k_normc<<<160, 256>>>();
    k_div<<<40960, 256>>>(outp);
}

// round 11
// speedup vs baseline: 1.0752x; 1.0752x over previous
#include <cuda_runtime.h>
#include <cuda_bf16.h>
#include <math.h>

#define BB 8
#define NN 1024
#define HH 128
#define NHD 4
#define DH 32
#define NCOE 50
#define NSC 4

typedef unsigned long long u64;

// ---------------- packed f32x2 helpers (Blackwell FFMA2 path) ----------------
__device__ __forceinline__ u64 f2pack(float lo, float hi) {
    u64 r;
    asm("mov.b64 %0, {%1, %2};" : "=l"(r) : "f"(lo), "f"(hi));
    return r;
}
__device__ __forceinline__ u64 f2dup(float x) {
    u64 r;
    asm("mov.b64 %0, {%1, %1};" : "=l"(r) : "f"(x));
    return r;
}
__device__ __forceinline__ void f2fma(u64& d, u64 a, u64 b) {
    asm("fma.rn.f32x2 %0, %1, %2, %0;" : "+l"(d) : "l"(a), "l"(b));
}
__device__ __forceinline__ void f2unpack(u64 v, float& lo, float& hi) {
    asm("mov.b64 {%0, %1}, %2;" : "=f"(lo), "=f"(hi) : "l"(v));
}

// ---------------- static device scratch (no allocations allowed) ----------------
__device__ __align__(16) float g_eig[BB * NN * HH];                  // 4 MB
__device__ __align__(16) float g_x[BB * NN * HH];                    // 4 MB
__device__ __align__(16) float g_qkv[BB * NN * 3 * HH];              // 12 MB (reused as FFN scratch)
__device__ __align__(16) float g_scores[(size_t)BB * NHD * NN * NN]; // 128 MB
__device__ __align__(16) float g_o[BB * NN * HH];                    // 4 MB
__device__ float g_rowsum[BB * HH];
__device__ float g_csc[BB * NCOE];
__device__ float g_cwv[BB * NCOE];
__device__ float g_cscl[BB * NSC];
__device__ __align__(16) float g_fsa[BB * NN * 8];
__device__ __align__(16) float g_normp[8][5 * BB * NN];
__device__ __align__(16) float g_norm[5 * BB * NN];

// ---------------- 1. sine encoding + eigw linear ----------------
__global__ void k_encode(const float* __restrict__ ev, const float* __restrict__ W,
                         const float* __restrict__ bias) {
    int tok = blockIdx.x;   // b*N+n
    int t = threadIdx.x;    // 0..127
    __shared__ float feat[129];
    float e = ev[tok];
    if (t < 64) {
        float div = expf(-(float)(2 * t) * (9.210340371976184f / 128.0f)); // ln(1e4)/H
        float pe = e * 100.0f * div;
        feat[1 + t] = sinf(pe);
        feat[65 + t] = cosf(pe);
    }
    if (t == 0) feat[0] = e;
    __syncthreads();
    float acc = bias[t];
    const float* w = W + t * 129;
#pragma unroll 4
    for (int j = 0; j < 129; j++) acc = fmaf(w[j], feat[j], acc);
    g_eig[(size_t)tok * HH + t] = acc;
}

// ---------------- layernorm ----------------
__global__ void k_ln(const float* __restrict__ in, float* __restrict__ out,
                     const float* __restrict__ g, const float* __restrict__ b) {
    int tok = blockIdx.x, t = threadIdx.x;
    float x = in[(size_t)tok * HH + t];
    __shared__ float r1[4], r2[4];
    float s = x;
#pragma unroll
    for (int o = 16; o > 0; o >>= 1) s += __shfl_xor_sync(0xffffffffu, s, o);
    if ((t & 31) == 0) r1[t >> 5] = s;
    __syncthreads();
    float mu = (r1[0] + r1[1] + r1[2] + r1[3]) * (1.0f / HH);
    float d = x - mu;
    float v = d * d;
#pragma unroll
    for (int o = 16; o > 0; o >>= 1) v += __shfl_xor_sync(0xffffffffu, v, o);
    if ((t & 31) == 0) r2[t >> 5] = v;
    __syncthreads();
    float var = (r2[0] + r2[1] + r2[2] + r2[3]) * (1.0f / HH);
    out[(size_t)tok * HH + t] = d * rsqrtf(var + 1e-5f) * g[t] + b[t];
}

// ---------------- generic dense: Y[M,O] = act(X[M,128] @ W[O,128]^T + b) (+R) ----------------
// grid (O/64, M/64), block 256, tile 64x64, micro 4x4, ktile 16
template <int ACT, bool RES>
__global__ __launch_bounds__(256) void k_dense(const float* __restrict__ X,
                                               const float* __restrict__ W,
                                               const float* __restrict__ bias,
                                               const float* __restrict__ R,
                                               float* __restrict__ Y, int O) {
    __shared__ float Xs[16][64];
    __shared__ float Ws[16][64];
    int t = threadIdx.x, tx = t & 15, ty = t >> 4;
    int m0 = blockIdx.y * 64, o0 = blockIdx.x * 64;
    float acc[4][4] = {};
    int r = t >> 2, kq = (t & 3) * 4;
    for (int k0 = 0; k0 < HH; k0 += 16) {
        __syncthreads();
        float4 xv = *(const float4*)&X[(size_t)(m0 + r) * HH + k0 + kq];
        Xs[kq + 0][r] = xv.x; Xs[kq + 1][r] = xv.y; Xs[kq + 2][r] = xv.z; Xs[kq + 3][r] = xv.w;
        float4 wv = *(const float4*)&W[(size_t)(o0 + r) * HH + k0 + kq];
        Ws[kq + 0][r] = wv.x; Ws[kq + 1][r] = wv.y; Ws[kq + 2][r] = wv.z; Ws[kq + 3][r] = wv.w;
        __syncthreads();
#pragma unroll
        for (int k = 0; k < 16; k++) {
            float4 a = *(const float4*)&Xs[k][ty * 4];
            float4 bb = *(const float4*)&Ws[k][tx * 4];
            float av[4] = {a.x, a.y, a.z, a.w};
            float bv[4] = {bb.x, bb.y, bb.z, bb.w};
#pragma unroll
            for (int i = 0; i < 4; i++)
#pragma unroll
                for (int j = 0; j < 4; j++) acc[i][j] = fmaf(av[i], bv[j], acc[i][j]);
        }
    }
#pragma unroll
    for (int i = 0; i < 4; i++) {
        int m = m0 + ty * 4 + i;
#pragma unroll
        for (int j = 0; j < 4; j++) {
            int o = o0 + tx * 4 + j;
            float v = acc[i][j] + bias[o];
            if (ACT == 1) v = 0.5f * v * (1.0f + erff(v * 0.70710678118654752f));
            if (RES) v += R[(size_t)m * O + o];
            Y[(size_t)m * O + o] = v;
        }
    }
}

// ---------------- attention: scores = q@k^T/sqrt(dh), masked ----------------
// grid (16 mtile, 16 ntile, 32 bh), block 256
__global__ __launch_bounds__(256) void k_scores(const int* __restrict__ length) {
    int bh = blockIdx.z;
    int b = bh >> 2, h = bh & 3;
    int n0 = blockIdx.y * 64, m0 = blockIdx.x * 64;
    __shared__ float Qs[32][64];
    __shared__ float Ks[32][64];
    int t = threadIdx.x, tx = t & 15, ty = t >> 4;
    {
        int r = t >> 2, kq = (t & 3) * 8;
        const float* qp = &g_qkv[((size_t)b * NN + (n0 + r)) * (3 * HH) + h * DH + kq];
        float4 v0 = *(const float4*)qp, v1 = *(const float4*)(qp + 4);
        Qs[kq + 0][r] = v0.x; Qs[kq + 1][r] = v0.y; Qs[kq + 2][r] = v0.z; Qs[kq + 3][r] = v0.w;
        Qs[kq + 4][r] = v1.x; Qs[kq + 5][r] = v1.y; Qs[kq + 6][r] = v1.z; Qs[kq + 7][r] = v1.w;
        const float* kp = &g_qkv[((size_t)b * NN + (m0 + r)) * (3 * HH) + HH + h * DH + kq];
        float4 k0v = *(const float4*)kp, k1v = *(const float4*)(kp + 4);
        Ks[kq + 0][r] = k0v.x; Ks[kq + 1][r] = k0v.y; Ks[kq + 2][r] = k0v.z; Ks[kq + 3][r] = k0v.w;
        Ks[kq + 4][r] = k1v.x; Ks[kq + 5][r] = k1v.y; Ks[kq + 6][r] = k1v.z; Ks[kq + 7][r] = k1v.w;
    }
    __syncthreads();
    float acc[4][4] = {};
#pragma unroll 8
    for (int k = 0; k < 32; k++) {
        float4 a = *(const float4*)&Qs[k][ty * 4];
        float4 bb = *(const float4*)&Ks[k][tx * 4];
        float av[4] = {a.x, a.y, a.z, a.w};
        float bv[4] = {bb.x, bb.y, bb.z, bb.w};
#pragma unroll
        for (int i = 0; i < 4; i++)
#pragma unroll
            for (int j = 0; j < 4; j++) acc[i][j] = fmaf(av[i], bv[j], acc[i][j]);
    }
    int len = length[b];
    float* S = g_scores + (size_t)bh * NN * NN;
    const float sc = 0.17677669529663688f; // 1/sqrt(32)
    int mb = m0 + tx * 4;
#pragma unroll
    for (int i = 0; i < 4; i++) {
        int n = n0 + ty * 4 + i;
        float4 v;
        v.x = (mb + 0 >= len) ? -1e9f : acc[i][0] * sc;
        v.y = (mb + 1 >= len) ? -1e9f : acc[i][1] * sc;
        v.z = (mb + 2 >= len) ? -1e9f : acc[i][2] * sc;
        v.w = (mb + 3 >= len) ? -1e9f : acc[i][3] * sc;
        *(float4*)&S[(size_t)n * NN + mb] = v;
    }
}

// ---------------- softmax over rows of 1024 ----------------
__global__ __launch_bounds__(256) void k_softmax() {
    size_t row = blockIdx.x;
    float4* p = (float4*)(g_scores + row * NN);
    int t = threadIdx.x;
    float4 v = p[t];
    __shared__ float redm[8], reds[8];
    float mx = fmaxf(fmaxf(v.x, v.y), fmaxf(v.z, v.w));
#pragma unroll
    for (int o = 16; o > 0; o >>= 1) mx = fmaxf(mx, __shfl_xor_sync(0xffffffffu, mx, o));
    if ((t & 31) == 0) redm[t >> 5] = mx;
    __syncthreads();
    mx = redm[0];
#pragma unroll
    for (int i = 1; i < 8; i++) mx = fmaxf(mx, redm[i]);
    v.x = __expf(v.x - mx); v.y = __expf(v.y - mx);
    v.z = __expf(v.z - mx); v.w = __expf(v.w - mx);
    float s = v.x + v.y + v.z + v.w;
#pragma unroll
    for (int o = 16; o > 0; o >>= 1) s += __shfl_xor_sync(0xffffffffu, s, o);
    if ((t & 31) == 0) reds[t >> 5] = s;
    __syncthreads();
    s = reds[0] + reds[1] + reds[2] + reds[3] + reds[4] + reds[5] + reds[6] + reds[7];
    float inv = 1.0f / s;
    v.x *= inv; v.y *= inv; v.z *= inv; v.w *= inv;
    p[t] = v;
}

// ---------------- O = attn @ v ----------------
// grid (16 ntiles, 32 bh), block 256; tile 64n x 32d
__global__ __launch_bounds__(256) void k_av() {
    int bh = blockIdx.y;
    int b = bh >> 2, h = bh & 3;
    int n0 = blockIdx.x * 64;
    __shared__ float Ss[32][64];
    __shared__ float Vs[32][32];
    int t = threadIdx.x, tx = t & 15, ty = t >> 4;
    const float* S = g_scores + (size_t)bh * NN * NN;
    float acc[4][2] = {};
    for (int k0 = 0; k0 < NN; k0 += 32) {
        __syncthreads();
        {
            int r = t >> 2, kq = (t & 3) * 8;
            const float* sp = &S[(size_t)(n0 + r) * NN + k0 + kq];
            float4 s0 = *(const float4*)sp, s1 = *(const float4*)(sp + 4);
            Ss[kq + 0][r] = s0.x; Ss[kq + 1][r] = s0.y; Ss[kq + 2][r] = s0.z; Ss[kq + 3][r] = s0.w;
            Ss[kq + 4][r] = s1.x; Ss[kq + 5][r] = s1.y; Ss[kq + 6][r] = s1.z; Ss[kq + 7][r] = s1.w;
        }
        if (t < 128) {
            int r = t >> 2, kq = (t & 3) * 8;
            const float* vp = &g_qkv[((size_t)b * NN + (k0 + r)) * (3 * HH) + 2 * HH + h * DH + kq];
            float4 v0 = *(const float4*)vp, v1 = *(const float4*)(vp + 4);
            *(float4*)&Vs[r][kq] = v0;
            *(float4*)&Vs[r][kq + 4] = v1;
        }
        __syncthreads();
#pragma unroll 8
        for (int k = 0; k < 32; k++) {
            float4 sn = *(const float4*)&Ss[k][ty * 4];
            float va = Vs[k][tx * 2], vb = Vs[k][tx * 2 + 1];
            float sv[4] = {sn.x, sn.y, sn.z, sn.w};
#pragma unroll
            for (int i = 0; i < 4; i++) {
                acc[i][0] = fmaf(sv[i], va, acc[i][0]);
                acc[i][1] = fmaf(sv[i], vb, acc[i][1]);
            }
        }
    }
#pragma unroll
    for (int i = 0; i < 4; i++) {
        size_t base = ((size_t)b * NN + (n0 + ty * 4 + i)) * HH + h * DH + tx * 2;
        g_o[base] = acc[i][0];
        g_o[base + 1] = acc[i][1];
    }
}

// ---------------- masked row-sum pool ----------------
__global__ void k_rowsum(const int* __restrict__ length) {
    int b = blockIdx.x, t = threadIdx.x; // 512 threads
    int h = t & 127, part = t >> 7;
    int len = length[b];
    float s = 0.0f;
    for (int n = part; n < len; n += 4) s += g_eig[(size_t)(b * NN + n) * HH + h];
    __shared__ float sm[512];
    sm[t] = s;
    __syncthreads();
    if (part == 0) g_rowsum[b * HH + h] = sm[h] + sm[128 + h] + sm[256 + h] + sm[384 + h];
}

// ---------------- decoders: pooled linears + sigmoid + normalize ----------------
__global__ void k_decode(const int* __restrict__ length,
                         const float* __restrict__ dscW, const float* __restrict__ dscB,
                         const float* __restrict__ dwavW, const float* __restrict__ dwavB,
                         const float* __restrict__ dsclW, const float* __restrict__ dsclB) {
    int b = blockIdx.x, t = threadIdx.x; // 128 threads
    __shared__ float rs[HH];
    __shared__ float s1[NCOE], s2[NCOE];
    __shared__ float sums[2];
    rs[t] = g_rowsum[b * HH + t];
    __syncthreads();
    float lenf = (float)length[b];
    float inv = 1.0f / (lenf + 1e-8f);
    float cs = 0.0f, cw = 0.0f;
    if (t < NCOE) {
        float a = dscB[t] * lenf, a2 = dwavB[t] * lenf;
        const float* w1 = dscW + t * HH;
        const float* w2 = dwavW + t * HH;
        for (int k = 0; k < HH; k++) {
            a = fmaf(rs[k], w1[k], a);
            a2 = fmaf(rs[k], w2[k], a2);
        }
        cs = 1.0f / (1.0f + expf(-a * inv));
        cw = 1.0f / (1.0f + expf(-a2 * inv));
        s1[t] = cs; s2[t] = cw;
    }
    if (t < NSC) {
        float a = dsclB[t] * lenf;
        const float* w = dsclW + t * HH;
        for (int k = 0; k < HH; k++) a = fmaf(rs[k], w[k], a);
        g_cscl[b * NSC + t] = 5.0f / (1.0f + expf(-a * inv));
    }
    __syncthreads();
    if (t == 0) {
        float x = 0.0f, y = 0.0f;
        for (int i = 0; i < NCOE; i++) { x += s1[i]; y += s2[i]; }
        sums[0] = x; sums[1] = y;
    }
    __syncthreads();
    if (t < NCOE) {
        g_csc[b * NCOE + t] = cs / (sums[0] + 1e-8f);
        g_cwv[b * NCOE + t] = cw / (sums[1] + 1e-8f);
    }
}

// ---------------- Chebyshev recurrences -> normalized fsa [B,N,5] (stride 8) ----------------
__global__ void k_fsa(const float* __restrict__ ev) {
    int b = blockIdx.y;
    int n = blockIdx.x * 256 + threadIdx.x;
    __shared__ float csc[NCOE], cwv[NCOE], scl[NSC];
    int t = threadIdx.x;
    if (t < NCOE) { csc[t] = g_csc[b * NCOE + t]; cwv[t] = g_cwv[b * NCOE + t]; }
    if (t < NSC) scl[t] = g_cscl[b * NSC + t];
    __syncthreads();
    float e = ev[b * NN + n];
    float f[5];
    {
        // scal series: to0=y, then odds of the scan
        float y = e - 1.0f;
        float te = 1.0f, to = y;
        float a = csc[0] * (0.5f * (1.0f - to));
        for (int c = 1; c < NCOE; c++) {
            te = 2.0f * y * to - te;
            to = 2.0f * y * te - to;
            a = fmaf(csc[c], 0.5f * (1.0f - to), a);
        }
        f[0] = a;
    }
#pragma unroll
    for (int s = 0; s < NSC; s++) {
        // wav series: te0=1, then evens of the scan
        float fw = e * scl[s];
        if (fw > 2.0f) fw = 0.0f;
        float y = fw - 1.0f;
        float te = 1.0f, to = y;
        float a = cwv[0] * (0.5f * (1.0f - te));
        for (int c = 1; c < NCOE; c++) {
            te = 2.0f * y * to - te;
            to = 2.0f * y * te - to;
            a = fmaf(cwv[c], 0.5f * (1.0f - te), a);
        }
        f[1 + s] = a;
    }
    float nr = sqrtf(f[0] * f[0] + f[1] * f[1] + f[2] * f[2] + f[3] * f[3] + f[4] * f[4]);
    float invn = 1.0f / (nr + 1e-8f);
    float* outp = &g_fsa[(size_t)(b * NN + n) * 8];
#pragma unroll
    for (int s = 0; s < 5; s++) outp[s] = f[s] * invn;
    outp[5] = 0.0f; outp[6] = 0.0f; outp[7] = 0.0f;
}

// ---------------- big symmetric 5-scale filter GEMM (FFMA2 mainloop) ----------------
// grid (136 tile-pairs ti<=tj, B), block 256; tile 64x64, micro 4x4 (i-packed f32x2), ktile 16
__global__ __launch_bounds__(256) void k_filters(const float* __restrict__ evc,
                                                 float* __restrict__ out) {
    int b = blockIdx.y;
    int idx = blockIdx.x;
    int ti = 0, rem = idx;
    while (rem >= 16 - ti) { rem -= 16 - ti; ti++; }
    int tj = ti + rem;
    const float* A = evc + (size_t)b * NN * NN;
    __shared__ float As[5][16][64];
    __shared__ float Bs[16][64];
    int t = threadIdx.x, tx = t & 15, ty = t >> 4;
    int n0 = ti * 64, m0 = tj * 64;
    // acc[s][p][j]: f32x2 packed over i; p=0 -> rows i=0(lo),1(hi); p=1 -> i=2(lo),3(hi)
    u64 acc[5][2][4] = {};
    int r = t >> 2, kq = (t & 3) * 4;
    const float* fs = g_fsa + (size_t)b * NN * 8;
    for (int k0 = 0; k0 < NN; k0 += 16) {
        __syncthreads();
        {
            float4 bv = *(const float4*)&A[(size_t)(m0 + r) * NN + k0 + kq];
            Bs[kq + 0][r] = bv.x; Bs[kq + 1][r] = bv.y; Bs[kq + 2][r] = bv.z; Bs[kq + 3][r] = bv.w;
            float4 av = *(const float4*)&A[(size_t)(n0 + r) * NN + k0 + kq];
            float a4[4] = {av.x, av.y, av.z, av.w};
#pragma unroll
            for (int kk = 0; kk < 4; kk++) {
                int k = k0 + kq + kk;
                float4 w4 = *(const float4*)&fs[(size_t)k * 8];
                float w5 = fs[(size_t)k * 8 + 4];
                As[0][kq + kk][r] = a4[kk] * w4.x;
                As[1][kq + kk][r] = a4[kk] * w4.y;
                As[2][kq + kk][r] = a4[kk] * w4.z;
                As[3][kq + kk][r] = a4[kk] * w4.w;
                As[4][kq + kk][r] = a4[kk] * w5;
            }
        }
        __syncthreads();
#pragma unroll 4
        for (int k = 0; k < 16; k++) {
            float4 bm = *(const float4*)&Bs[k][tx * 4];
            u64 bd0 = f2dup(bm.x), bd1 = f2dup(bm.y), bd2 = f2dup(bm.z), bd3 = f2dup(bm.w);
#pragma unroll
            for (int s = 0; s < 5; s++) {
                float4 an = *(const float4*)&As[s][k][ty * 4];
                u64 a01 = f2pack(an.x, an.y);
                u64 a23 = f2pack(an.z, an.w);
                f2fma(acc[s][0][0], a01, bd0);
                f2fma(acc[s][0][1], a01, bd1);
                f2fma(acc[s][0][2], a01, bd2);
                f2fma(acc[s][0][3], a01, bd3);
                f2fma(acc[s][1][0], a23, bd0);
                f2fma(acc[s][1][1], a23, bd1);
                f2fma(acc[s][1][2], a23, bd2);
                f2fma(acc[s][1][3], a23, bd3);
            }
        }
    }
    const size_t PLANE = (size_t)NN * NN;
#pragma unroll
    for (int s = 0; s < 5; s++) {
        float* base = out + ((size_t)s * BB + b) * PLANE;
        float f[4][4];
#pragma unroll
        for (int j = 0; j < 4; j++) {
            f2unpack(acc[s][0][j], f[0][j], f[1][j]);
            f2unpack(acc[s][1][j], f[2][j], f[3][j]);
        }
#pragma unroll
        for (int i = 0; i < 4; i++) {
            *(float4*)&base[(size_t)(n0 + ty * 4 + i) * NN + m0 + tx * 4] =
                make_float4(f[i][0], f[i][1], f[i][2], f[i][3]);
        }
        if (ti != tj) {
            // mirror: each thread owns rows m0+tx*4+j, contiguous cols n0+ty*4..+3 -> float4 stores
#pragma unroll
            for (int j = 0; j < 4; j++) {
                *(float4*)&base[(size_t)(m0 + tx * 4 + j) * NN + n0 + ty * 4] =
                    make_float4(f[0][j], f[1][j], f[2][j], f[3][j]);
            }
        }
    }
}

// ---------------- column norms (over n) in two phases, then scale ----------------
__global__ void k_normp(const float* __restrict__ out) {
    int m = blockIdx.x * 256 + threadIdx.x;
    int sb = blockIdx.y;  // s*B+b, 0..39
    int np = blockIdx.z;  // 0..7
    const float* base = out + (size_t)sb * NN * NN;
    float a = 0.0f;
    int nEnd = np * 128 + 128;
    for (int n = np * 128; n < nEnd; n++) {
        float v = base[(size_t)n * NN + m];
        a = fmaf(v, v, a);
    }
    g_normp[np][sb * NN + m] = a;
}

__global__ void k_normc() {
    int i = blockIdx.x * 256 + threadIdx.x; // < 40960
    float a = 0.0f;
#pragma unroll
    for (int p = 0; p < 8; p++) a += g_normp[p][i];
    g_norm[i] = 1.0f / fmaxf(sqrtf(a), 1e-12f);   // store reciprocal
}

__global__ void k_div(float* __restrict__ out) {
    size_t i = (size_t)blockIdx.x * 256 + threadIdx.x; // float4 index
    size_t gidx = i * 4;
    int sb = (int)(gidx >> 20);        // plane of N*N = 1<<20 elements
    int m = (int)(gidx & (NN - 1));
    float4 v = ((float4*)out)[i];
    float4 nv = *(const float4*)&g_norm[sb * NN + m];
    v.x *= nv.x; v.y *= nv.y; v.z *= nv.z; v.w *= nv.w;
    ((float4*)out)[i] = v;
}

// ---------------- launch ----------------
extern "C" void kernel_launch(void* const* d_in, const int* in_sizes, int n_in,
                              void* d_out, int out_size) {
    const float* eigenvalue = (const float*)d_in[0];
    const float* eigenvector = (const float*)d_in[1];
    const float* eigw_W = (const float*)d_in[2];
    const float* eigw_b = (const float*)d_in[3];
    const float* ln1_g = (const float*)d_in[4];
    const float* ln1_b = (const float*)d_in[5];
    const float* qkv_W = (const float*)d_in[6];
    const float* qkv_b = (const float*)d_in[7];
    const float* out_W = (const float*)d_in[8];
    const float* out_b = (const float*)d_in[9];
    const float* ln2_g = (const float*)d_in[10];
    const float* ln2_b = (const float*)d_in[11];
    const float* ffn1_W = (const float*)d_in[12];
    const float* ffn1_b = (const float*)d_in[13];
    const float* ffn2_W = (const float*)d_in[14];
    const float* ffn2_b = (const float*)d_in[15];
    const float* dsc_W = (const float*)d_in[16];
    const float* dsc_b = (const float*)d_in[17];
    const float* dwav_W = (const float*)d_in[18];
    const float* dwav_b = (const float*)d_in[19];
    const float* dscl_W = (const float*)d_in[20];
    const float* dscl_b = (const float*)d_in[21];
    const int* length = (const int*)d_in[22];
    float* outp = (float*)d_out;

    float *p_eig, *p_x, *p_qkv, *p_o;
    cudaGetSymbolAddress((void**)&p_eig, g_eig);
    cudaGetSymbolAddress((void**)&p_x, g_x);
    cudaGetSymbolAddress((void**)&p_qkv, g_qkv);
    cudaGetSymbolAddress((void**)&p_o, g_o);

    // encoder
    k_encode<<<BB * NN, HH>>>(eigenvalue, eigw_W, eigw_b);
    // MHA block
    k_ln<<<BB * NN, HH>>>(p_eig, p_x, ln1_g, ln1_b);
    k_dense<0, false><<<dim3(6, 128), 256>>>(p_x, qkv_W, qkv_b, nullptr, p_qkv, 3 * HH);
    k_scores<<<dim3(16, 16, BB * NHD), 256>>>(length);
    k_softmax<<<BB * NHD * NN, 256>>>();
    k_av<<<dim3(16, BB * NHD), 256>>>();
    k_dense<0, true><<<dim3(2, 128), 256>>>(p_o, out_W, out_b, p_eig, p_eig, HH);
    // FFN block
    k_ln<<<BB * NN, HH>>>(p_eig, p_x, ln2_g, ln2_b);
    k_dense<1, false><<<dim3(2, 128), 256>>>(p_x, ffn1_W, ffn1_b, nullptr, p_qkv, HH);
    k_dense<0, true><<<dim3(2, 128), 256>>>(p_qkv, ffn2_W, ffn2_b, p_eig, p_eig, HH);
    // decoders
    k_rowsum<<<BB, 512>>>(length);
    k_decode<<<BB, 128>>>(length, dsc_W, dsc_b, dwav_W, dwav_b, dscl_W, dscl_b);
    // spectral filters
    k_fsa<<<dim3(4, BB), 256>>>(eigenvalue);
    k_filters<<<dim3(136, BB), 256>>>(eigenvector, outp);
    // normalize columns
    k_normp<<<dim3(4, 5 * BB, 8), 256>>>(outp);
    k_normc<<<160, 256>>>();
    k_div<<<40960, 256>>>(outp);
}

// round 14
// speedup vs baseline: 1.8261x; 1.6984x over previous
#include <cuda_runtime.h>
#include <cuda_bf16.h>
#include <cuda_fp16.h>
#include <math.h>
#include <stdint.h>

#define BB 8
#define NN 1024
#define HH 128
#define NHD 4
#define DH 32
#define NCOE 50
#define NSC 4

// ---------------- static device scratch (no allocations allowed) ----------------
__device__ __align__(16) float g_eig[BB * NN * HH];                  // 4 MB
__device__ __align__(16) float g_x[BB * NN * HH];                    // 4 MB
__device__ __align__(16) float g_qkv[BB * NN * 3 * HH];              // 12 MB
__device__ __align__(16) float g_scores[(size_t)BB * NHD * NN * NN]; // 128 MB
__device__ __align__(16) float g_o[BB * NN * HH];                    // 4 MB
__device__ float g_rowsum[BB * HH];
__device__ float g_csc[BB * NCOE];
__device__ float g_cwv[BB * NCOE];
__device__ float g_cscl[BB * NSC];
__device__ __align__(16) float g_fsa[BB * NN * 8];
__device__ __align__(16) float g_normp[8][5 * BB * NN];
__device__ __align__(16) float g_norm[5 * BB * NN];
// fp16 operands for tensor-core filter GEMM
__device__ __align__(16) __half g_Bh[BB][NN * NN];        // 16 MB  fp16(evc)
__device__ __align__(16) __half g_Ash[5][BB][NN * NN];    // 80 MB  fp16(evc*w_s) hi
__device__ __align__(16) __half g_Asl[5][BB][NN * NN];    // 80 MB  residual lo

// ---------------- 1. sine encoding + eigw linear ----------------
__global__ void k_encode(const float* __restrict__ ev, const float* __restrict__ W,
                         const float* __restrict__ bias) {
    int tok = blockIdx.x;
    int t = threadIdx.x;
    __shared__ float feat[129];
    float e = ev[tok];
    if (t < 64) {
        float div = expf(-(float)(2 * t) * (9.210340371976184f / 128.0f));
        float pe = e * 100.0f * div;
        feat[1 + t] = sinf(pe);
        feat[65 + t] = cosf(pe);
    }
    if (t == 0) feat[0] = e;
    __syncthreads();
    float acc = bias[t];
    const float* w = W + t * 129;
#pragma unroll 4
    for (int j = 0; j < 129; j++) acc = fmaf(w[j], feat[j], acc);
    g_eig[(size_t)tok * HH + t] = acc;
}

// ---------------- layernorm ----------------
__global__ void k_ln(const float* __restrict__ in, float* __restrict__ out,
                     const float* __restrict__ g, const float* __restrict__ b) {
    int tok = blockIdx.x, t = threadIdx.x;
    float x = in[(size_t)tok * HH + t];
    __shared__ float r1[4], r2[4];
    float s = x;
#pragma unroll
    for (int o = 16; o > 0; o >>= 1) s += __shfl_xor_sync(0xffffffffu, s, o);
    if ((t & 31) == 0) r1[t >> 5] = s;
    __syncthreads();
    float mu = (r1[0] + r1[1] + r1[2] + r1[3]) * (1.0f / HH);
    float d = x - mu;
    float v = d * d;
#pragma unroll
    for (int o = 16; o > 0; o >>= 1) v += __shfl_xor_sync(0xffffffffu, v, o);
    if ((t & 31) == 0) r2[t >> 5] = v;
    __syncthreads();
    float var = (r2[0] + r2[1] + r2[2] + r2[3]) * (1.0f / HH);
    out[(size_t)tok * HH + t] = d * rsqrtf(var + 1e-5f) * g[t] + b[t];
}

// ---------------- generic dense ----------------
template <int ACT, bool RES>
__global__ __launch_bounds__(256) void k_dense(const float* __restrict__ X,
                                               const float* __restrict__ W,
                                               const float* __restrict__ bias,
                                               const float* __restrict__ R,
                                               float* __restrict__ Y, int O) {
    __shared__ float Xs[16][64];
    __shared__ float Ws[16][64];
    int t = threadIdx.x, tx = t & 15, ty = t >> 4;
    int m0 = blockIdx.y * 64, o0 = blockIdx.x * 64;
    float acc[4][4] = {};
    int r = t >> 2, kq = (t & 3) * 4;
    for (int k0 = 0; k0 < HH; k0 += 16) {
        __syncthreads();
        float4 xv = *(const float4*)&X[(size_t)(m0 + r) * HH + k0 + kq];
        Xs[kq + 0][r] = xv.x; Xs[kq + 1][r] = xv.y; Xs[kq + 2][r] = xv.z; Xs[kq + 3][r] = xv.w;
        float4 wv = *(const float4*)&W[(size_t)(o0 + r) * HH + k0 + kq];
        Ws[kq + 0][r] = wv.x; Ws[kq + 1][r] = wv.y; Ws[kq + 2][r] = wv.z; Ws[kq + 3][r] = wv.w;
        __syncthreads();
#pragma unroll
        for (int k = 0; k < 16; k++) {
            float4 a = *(const float4*)&Xs[k][ty * 4];
            float4 bb = *(const float4*)&Ws[k][tx * 4];
            float av[4] = {a.x, a.y, a.z, a.w};
            float bv[4] = {bb.x, bb.y, bb.z, bb.w};
#pragma unroll
            for (int i = 0; i < 4; i++)
#pragma unroll
                for (int j = 0; j < 4; j++) acc[i][j] = fmaf(av[i], bv[j], acc[i][j]);
        }
    }
#pragma unroll
    for (int i = 0; i < 4; i++) {
        int m = m0 + ty * 4 + i;
#pragma unroll
        for (int j = 0; j < 4; j++) {
            int o = o0 + tx * 4 + j;
            float v = acc[i][j] + bias[o];
            if (ACT == 1) v = 0.5f * v * (1.0f + erff(v * 0.70710678118654752f));
            if (RES) v += R[(size_t)m * O + o];
            Y[(size_t)m * O + o] = v;
        }
    }
}

// ---------------- attention: scores ----------------
__global__ __launch_bounds__(256) void k_scores(const int* __restrict__ length) {
    int bh = blockIdx.z;
    int b = bh >> 2, h = bh & 3;
    int n0 = blockIdx.y * 64, m0 = blockIdx.x * 64;
    __shared__ float Qs[32][64];
    __shared__ float Ks[32][64];
    int t = threadIdx.x, tx = t & 15, ty = t >> 4;
    {
        int r = t >> 2, kq = (t & 3) * 8;
        const float* qp = &g_qkv[((size_t)b * NN + (n0 + r)) * (3 * HH) + h * DH + kq];
        float4 v0 = *(const float4*)qp, v1 = *(const float4*)(qp + 4);
        Qs[kq + 0][r] = v0.x; Qs[kq + 1][r] = v0.y; Qs[kq + 2][r] = v0.z; Qs[kq + 3][r] = v0.w;
        Qs[kq + 4][r] = v1.x; Qs[kq + 5][r] = v1.y; Qs[kq + 6][r] = v1.z; Qs[kq + 7][r] = v1.w;
        const float* kp = &g_qkv[((size_t)b * NN + (m0 + r)) * (3 * HH) + HH + h * DH + kq];
        float4 k0v = *(const float4*)kp, k1v = *(const float4*)(kp + 4);
        Ks[kq + 0][r] = k0v.x; Ks[kq + 1][r] = k0v.y; Ks[kq + 2][r] = k0v.z; Ks[kq + 3][r] = k0v.w;
        Ks[kq + 4][r] = k1v.x; Ks[kq + 5][r] = k1v.y; Ks[kq + 6][r] = k1v.z; Ks[kq + 7][r] = k1v.w;
    }
    __syncthreads();
    float acc[4][4] = {};
#pragma unroll 8
    for (int k = 0; k < 32; k++) {
        float4 a = *(const float4*)&Qs[k][ty * 4];
        float4 bb = *(const float4*)&Ks[k][tx * 4];
        float av[4] = {a.x, a.y, a.z, a.w};
        float bv[4] = {bb.x, bb.y, bb.z, bb.w};
#pragma unroll
        for (int i = 0; i < 4; i++)
#pragma unroll
            for (int j = 0; j < 4; j++) acc[i][j] = fmaf(av[i], bv[j], acc[i][j]);
    }
    int len = length[b];
    float* S = g_scores + (size_t)bh * NN * NN;
    const float sc = 0.17677669529663688f;
    int mb = m0 + tx * 4;
#pragma unroll
    for (int i = 0; i < 4; i++) {
        int n = n0 + ty * 4 + i;
        float4 v;
        v.x = (mb + 0 >= len) ? -1e9f : acc[i][0] * sc;
        v.y = (mb + 1 >= len) ? -1e9f : acc[i][1] * sc;
        v.z = (mb + 2 >= len) ? -1e9f : acc[i][2] * sc;
        v.w = (mb + 3 >= len) ? -1e9f : acc[i][3] * sc;
        *(float4*)&S[(size_t)n * NN + mb] = v;
    }
}

// ---------------- softmax ----------------
__global__ __launch_bounds__(256) void k_softmax() {
    size_t row = blockIdx.x;
    float4* p = (float4*)(g_scores + row * NN);
    int t = threadIdx.x;
    float4 v = p[t];
    __shared__ float redm[8], reds[8];
    float mx = fmaxf(fmaxf(v.x, v.y), fmaxf(v.z, v.w));
#pragma unroll
    for (int o = 16; o > 0; o >>= 1) mx = fmaxf(mx, __shfl_xor_sync(0xffffffffu, mx, o));
    if ((t & 31) == 0) redm[t >> 5] = mx;
    __syncthreads();
    mx = redm[0];
#pragma unroll
    for (int i = 1; i < 8; i++) mx = fmaxf(mx, redm[i]);
    v.x = __expf(v.x - mx); v.y = __expf(v.y - mx);
    v.z = __expf(v.z - mx); v.w = __expf(v.w - mx);
    float s = v.x + v.y + v.z + v.w;
#pragma unroll
    for (int o = 16; o > 0; o >>= 1) s += __shfl_xor_sync(0xffffffffu, s, o);
    if ((t & 31) == 0) reds[t >> 5] = s;
    __syncthreads();
    s = reds[0] + reds[1] + reds[2] + reds[3] + reds[4] + reds[5] + reds[6] + reds[7];
    float inv = 1.0f / s;
    v.x *= inv; v.y *= inv; v.z *= inv; v.w *= inv;
    p[t] = v;
}

// ---------------- O = attn @ v ----------------
__global__ __launch_bounds__(256) void k_av() {
    int bh = blockIdx.y;
    int b = bh >> 2, h = bh & 3;
    int n0 = blockIdx.x * 64;
    __shared__ float Ss[32][64];
    __shared__ float Vs[32][32];
    int t = threadIdx.x, tx = t & 15, ty = t >> 4;
    const float* S = g_scores + (size_t)bh * NN * NN;
    float acc[4][2] = {};
    for (int k0 = 0; k0 < NN; k0 += 32) {
        __syncthreads();
        {
            int r = t >> 2, kq = (t & 3) * 8;
            const float* sp = &S[(size_t)(n0 + r) * NN + k0 + kq];
            float4 s0 = *(const float4*)sp, s1 = *(const float4*)(sp + 4);
            Ss[kq + 0][r] = s0.x; Ss[kq + 1][r] = s0.y; Ss[kq + 2][r] = s0.z; Ss[kq + 3][r] = s0.w;
            Ss[kq + 4][r] = s1.x; Ss[kq + 5][r] = s1.y; Ss[kq + 6][r] = s1.z; Ss[kq + 7][r] = s1.w;
        }
        if (t < 128) {
            int r = t >> 2, kq = (t & 3) * 8;
            const float* vp = &g_qkv[((size_t)b * NN + (k0 + r)) * (3 * HH) + 2 * HH + h * DH + kq];
            float4 v0 = *(const float4*)vp, v1 = *(const float4*)(vp + 4);
            *(float4*)&Vs[r][kq] = v0;
            *(float4*)&Vs[r][kq + 4] = v1;
        }
        __syncthreads();
#pragma unroll 8
        for (int k = 0; k < 32; k++) {
            float4 sn = *(const float4*)&Ss[k][ty * 4];
            float va = Vs[k][tx * 2], vb = Vs[k][tx * 2 + 1];
            float sv[4] = {sn.x, sn.y, sn.z, sn.w};
#pragma unroll
            for (int i = 0; i < 4; i++) {
                acc[i][0] = fmaf(sv[i], va, acc[i][0]);
                acc[i][1] = fmaf(sv[i], vb, acc[i][1]);
            }
        }
    }
#pragma unroll
    for (int i = 0; i < 4; i++) {
        size_t base = ((size_t)b * NN + (n0 + ty * 4 + i)) * HH + h * DH + tx * 2;
        g_o[base] = acc[i][0];
        g_o[base + 1] = acc[i][1];
    }
}

// ---------------- masked row-sum pool ----------------
__global__ void k_rowsum(const int* __restrict__ length) {
    int b = blockIdx.x, t = threadIdx.x;
    int h = t & 127, part = t >> 7;
    int len = length[b];
    float s = 0.0f;
    for (int n = part; n < len; n += 4) s += g_eig[(size_t)(b * NN + n) * HH + h];
    __shared__ float sm[512];
    sm[t] = s;
    __syncthreads();
    if (part == 0) g_rowsum[b * HH + h] = sm[h] + sm[128 + h] + sm[256 + h] + sm[384 + h];
}

// ---------------- decoders ----------------
__global__ void k_decode(const int* __restrict__ length,
                         const float* __restrict__ dscW, const float* __restrict__ dscB,
                         const float* __restrict__ dwavW, const float* __restrict__ dwavB,
                         const float* __restrict__ dsclW, const float* __restrict__ dsclB) {
    int b = blockIdx.x, t = threadIdx.x;
    __shared__ float rs[HH];
    __shared__ float s1[NCOE], s2[NCOE];
    __shared__ float sums[2];
    rs[t] = g_rowsum[b * HH + t];
    __syncthreads();
    float lenf = (float)length[b];
    float inv = 1.0f / (lenf + 1e-8f);
    float cs = 0.0f, cw = 0.0f;
    if (t < NCOE) {
        float a = dscB[t] * lenf, a2 = dwavB[t] * lenf;
        const float* w1 = dscW + t * HH;
        const float* w2 = dwavW + t * HH;
        for (int k = 0; k < HH; k++) {
            a = fmaf(rs[k], w1[k], a);
            a2 = fmaf(rs[k], w2[k], a2);
        }
        cs = 1.0f / (1.0f + expf(-a * inv));
        cw = 1.0f / (1.0f + expf(-a2 * inv));
        s1[t] = cs; s2[t] = cw;
    }
    if (t < NSC) {
        float a = dsclB[t] * lenf;
        const float* w = dsclW + t * HH;
        for (int k = 0; k < HH; k++) a = fmaf(rs[k], w[k], a);
        g_cscl[b * NSC + t] = 5.0f / (1.0f + expf(-a * inv));
    }
    __syncthreads();
    if (t == 0) {
        float x = 0.0f, y = 0.0f;
        for (int i = 0; i < NCOE; i++) { x += s1[i]; y += s2[i]; }
        sums[0] = x; sums[1] = y;
    }
    __syncthreads();
    if (t < NCOE) {
        g_csc[b * NCOE + t] = cs / (sums[0] + 1e-8f);
        g_cwv[b * NCOE + t] = cw / (sums[1] + 1e-8f);
    }
}

// ---------------- Chebyshev -> normalized fsa ----------------
__global__ void k_fsa(const float* __restrict__ ev) {
    int b = blockIdx.y;
    int n = blockIdx.x * 256 + threadIdx.x;
    __shared__ float csc[NCOE], cwv[NCOE], scl[NSC];
    int t = threadIdx.x;
    if (t < NCOE) { csc[t] = g_csc[b * NCOE + t]; cwv[t] = g_cwv[b * NCOE + t]; }
    if (t < NSC) scl[t] = g_cscl[b * NSC + t];
    __syncthreads();
    float e = ev[b * NN + n];
    float f[5];
    {
        float y = e - 1.0f;
        float te = 1.0f, to = y;
        float a = csc[0] * (0.5f * (1.0f - to));
        for (int c = 1; c < NCOE; c++) {
            te = 2.0f * y * to - te;
            to = 2.0f * y * te - to;
            a = fmaf(csc[c], 0.5f * (1.0f - to), a);
        }
        f[0] = a;
    }
#pragma unroll
    for (int s = 0; s < NSC; s++) {
        float fw = e * scl[s];
        if (fw > 2.0f) fw = 0.0f;
        float y = fw - 1.0f;
        float te = 1.0f, to = y;
        float a = cwv[0] * (0.5f * (1.0f - te));
        for (int c = 1; c < NCOE; c++) {
            te = 2.0f * y * to - te;
            to = 2.0f * y * te - to;
            a = fmaf(cwv[c], 0.5f * (1.0f - te), a);
        }
        f[1 + s] = a;
    }
    float nr = sqrtf(f[0] * f[0] + f[1] * f[1] + f[2] * f[2] + f[3] * f[3] + f[4] * f[4]);
    float invn = 1.0f / (nr + 1e-8f);
    float* outp = &g_fsa[(size_t)(b * NN + n) * 8];
#pragma unroll
    for (int s = 0; s < 5; s++) outp[s] = f[s] * invn;
    outp[5] = 0.0f; outp[6] = 0.0f; outp[7] = 0.0f;
}

// ---------------- B = fp16(evc) ----------------
__global__ void k_prepB(const float* __restrict__ evc) {
    size_t i = (size_t)blockIdx.x * 256 + threadIdx.x; // float4 index over 8M
    size_t g = i * 4;
    int b = (int)(g >> 20);
    int nk = (int)(g & ((1u << 20) - 1));
    float4 v = ((const float4*)evc)[i];
    __half2* p = (__half2*)&g_Bh[b][nk];
    p[0] = __floats2half2_rn(v.x, v.y);
    p[1] = __floats2half2_rn(v.z, v.w);
}

// ---------------- Ash/Asl = fp16 hi/lo of evc * w_s[k] ----------------
__global__ void k_prepAs(const float* __restrict__ evc) {
    size_t i = (size_t)blockIdx.x * 256 + threadIdx.x;
    size_t g = i * 4;
    int b = (int)(g >> 20);
    int nk = (int)(g & ((1u << 20) - 1));
    int k0 = nk & (NN - 1);
    float4 v = ((const float4*)evc)[i];
    float a[4] = {v.x, v.y, v.z, v.w};
    float w[4][5];
#pragma unroll
    for (int kk = 0; kk < 4; kk++) {
        const float* fr = &g_fsa[(size_t)(b * NN + k0 + kk) * 8];
        float4 w4 = *(const float4*)fr;
        w[kk][0] = w4.x; w[kk][1] = w4.y; w[kk][2] = w4.z; w[kk][3] = w4.w;
        w[kk][4] = fr[4];
    }
#pragma unroll
    for (int s = 0; s < 5; s++) {
        __half h[4], l[4];
#pragma unroll
        for (int kk = 0; kk < 4; kk++) {
            float vv = a[kk] * w[kk][s];
            h[kk] = __float2half_rn(vv);
            l[kk] = __float2half_rn(vv - __half2float(h[kk]));
        }
        __half2* ph = (__half2*)&g_Ash[s][b][nk];
        ph[0] = __halves2half2(h[0], h[1]);
        ph[1] = __halves2half2(h[2], h[3]);
        __half2* pl = (__half2*)&g_Asl[s][b][nk];
        pl[0] = __halves2half2(l[0], l[1]);
        pl[1] = __halves2half2(l[2], l[3]);
    }
}

// ---------------- HMMA filter GEMM: C[n][m] = sum_k (Ash+Asl)[n][k] * Bh[m][k] ----------------
// grid (36 tile pairs ti<=tj, 40 = s*8+b), block 256 (8 warps), CTA tile 128x128,
// warp tile 64 rows x 32 cols, K-chunk 64 fp16 in smem (stride 72 to kill bank conflicts).
#define STR 72
#define SMEM_MMA (3 * 128 * STR * 2)

__device__ __forceinline__ void hmma(float* d, uint32_t a0, uint32_t a1, uint32_t a2, uint32_t a3,
                                     uint32_t b0, uint32_t b1) {
    asm volatile(
        "mma.sync.aligned.m16n8k16.row.col.f32.f16.f16.f32 "
        "{%0,%1,%2,%3}, {%4,%5,%6,%7}, {%8,%9}, {%0,%1,%2,%3};"
        : "+f"(d[0]), "+f"(d[1]), "+f"(d[2]), "+f"(d[3])
        : "r"(a0), "r"(a1), "r"(a2), "r"(a3), "r"(b0), "r"(b1));
}

__global__ __launch_bounds__(256) void k_mma(float* __restrict__ out) {
    extern __shared__ __half sm[];
    __half* Ah = sm;
    __half* Al = sm + 128 * STR;
    __half* Bt = sm + 2 * 128 * STR;

    int idx = blockIdx.x;
    int ti = 0, rem = idx;
    while (rem >= 8 - ti) { rem -= 8 - ti; ti++; }
    int tj = ti + rem;
    int z = blockIdx.y;
    int s = z >> 3, b = z & 7;
    const __half* pAh = g_Ash[s][b];
    const __half* pAl = g_Asl[s][b];
    const __half* pB = g_Bh[b];

    int t = threadIdx.x, wid = t >> 5, lane = t & 31;
    int grp = lane >> 2, tig = lane & 3;
    int wr = (wid & 1) * 64;    // warp row offset (n)
    int wc = (wid >> 1) * 32;   // warp col offset (m)
    int n0 = ti * 128, m0 = tj * 128;

    int crow = t >> 1, chalf = t & 1; // copy: 256 threads -> 128 rows x 2 halves of 64B

    float acc[4][4][4] = {};

    for (int kc = 0; kc < NN; kc += 64) {
        __syncthreads();
        {
            const __half* sA = pAh + (size_t)(n0 + crow) * NN + kc + chalf * 32;
            const __half* sL = pAl + (size_t)(n0 + crow) * NN + kc + chalf * 32;
            const __half* sB = pB + (size_t)(m0 + crow) * NN + kc + chalf * 32;
            uint4* dA = (uint4*)&Ah[crow * STR + chalf * 32];
            uint4* dL = (uint4*)&Al[crow * STR + chalf * 32];
            uint4* dB = (uint4*)&Bt[crow * STR + chalf * 32];
#pragma unroll
            for (int q = 0; q < 4; q++) {
                dA[q] = ((const uint4*)sA)[q];
                dL[q] = ((const uint4*)sL)[q];
                dB[q] = ((const uint4*)sB)[q];
            }
        }
        __syncthreads();
#pragma unroll
        for (int ks = 0; ks < 4; ks++) {
            int kk = ks * 16;
            uint32_t bf[4][2];
#pragma unroll
            for (int jc = 0; jc < 4; jc++) {
                int mrow = wc + jc * 8 + grp;
                bf[jc][0] = *(const uint32_t*)&Bt[mrow * STR + kk + tig * 2];
                bf[jc][1] = *(const uint32_t*)&Bt[mrow * STR + kk + 8 + tig * 2];
            }
#pragma unroll
            for (int ir = 0; ir < 4; ir++) {
                int r0 = wr + ir * 16 + grp;
                uint32_t ah0 = *(const uint32_t*)&Ah[r0 * STR + kk + tig * 2];
                uint32_t ah1 = *(const uint32_t*)&Ah[(r0 + 8) * STR + kk + tig * 2];
                uint32_t ah2 = *(const uint32_t*)&Ah[r0 * STR + kk + 8 + tig * 2];
                uint32_t ah3 = *(const uint32_t*)&Ah[(r0 + 8) * STR + kk + 8 + tig * 2];
                uint32_t al0 = *(const uint32_t*)&Al[r0 * STR + kk + tig * 2];
                uint32_t al1 = *(const uint32_t*)&Al[(r0 + 8) * STR + kk + tig * 2];
                uint32_t al2 = *(const uint32_t*)&Al[r0 * STR + kk + 8 + tig * 2];
                uint32_t al3 = *(const uint32_t*)&Al[(r0 + 8) * STR + kk + 8 + tig * 2];
#pragma unroll
                for (int jc = 0; jc < 4; jc++) {
                    hmma(acc[ir][jc], ah0, ah1, ah2, ah3, bf[jc][0], bf[jc][1]);
                    hmma(acc[ir][jc], al0, al1, al2, al3, bf[jc][0], bf[jc][1]);
                }
            }
        }
    }

    float* base = out + ((size_t)(s * BB + b) << 20);
#pragma unroll
    for (int ir = 0; ir < 4; ir++) {
        int n = n0 + wr + ir * 16 + grp;
#pragma unroll
        for (int jc = 0; jc < 4; jc++) {
            int m = m0 + wc + jc * 8 + tig * 2;
            float* d = acc[ir][jc];
            *(float2*)&base[(size_t)n * NN + m] = make_float2(d[0], d[1]);
            *(float2*)&base[(size_t)(n + 8) * NN + m] = make_float2(d[2], d[3]);
            if (ti != tj) {
                base[(size_t)m * NN + n] = d[0];
                base[(size_t)(m + 1) * NN + n] = d[1];
                base[(size_t)m * NN + n + 8] = d[2];
                base[(size_t)(m + 1) * NN + n + 8] = d[3];
            }
        }
    }
}

// ---------------- column norms, then scale ----------------
__global__ void k_normp(const float* __restrict__ out) {
    int m = blockIdx.x * 256 + threadIdx.x;
    int sb = blockIdx.y;
    int np = blockIdx.z;
    const float* base = out + (size_t)sb * NN * NN;
    float a = 0.0f;
    int nEnd = np * 128 + 128;
    for (int n = np * 128; n < nEnd; n++) {
        float v = base[(size_t)n * NN + m];
        a = fmaf(v, v, a);
    }
    g_normp[np][sb * NN + m] = a;
}

__global__ void k_normc() {
    int i = blockIdx.x * 256 + threadIdx.x;
    float a = 0.0f;
#pragma unroll
    for (int p = 0; p < 8; p++) a += g_normp[p][i];
    g_norm[i] = 1.0f / fmaxf(sqrtf(a), 1e-12f);
}

__global__ void k_div(float* __restrict__ out) {
    size_t i = (size_t)blockIdx.x * 256 + threadIdx.x;
    size_t gidx = i * 4;
    int sb = (int)(gidx >> 20);
    int m = (int)(gidx & (NN - 1));
    float4 v = ((float4*)out)[i];
    float4 nv = *(const float4*)&g_norm[sb * NN + m];
    v.x *= nv.x; v.y *= nv.y; v.z *= nv.z; v.w *= nv.w;
    ((float4*)out)[i] = v;
}

// ---------------- launch ----------------
extern "C" void kernel_launch(void* const* d_in, const int* in_sizes, int n_in,
                              void* d_out, int out_size) {
    const float* eigenvalue = (const float*)d_in[0];
    const float* eigenvector = (const float*)d_in[1];
    const float* eigw_W = (const float*)d_in[2];
    const float* eigw_b = (const float*)d_in[3];
    const float* ln1_g = (const float*)d_in[4];
    const float* ln1_b = (const float*)d_in[5];
    const float* qkv_W = (const float*)d_in[6];
    const float* qkv_b = (const float*)d_in[7];
    const float* out_W = (const float*)d_in[8];
    const float* out_b = (const float*)d_in[9];
    const float* ln2_g = (const float*)d_in[10];
    const float* ln2_b = (const float*)d_in[11];
    const float* ffn1_W = (const float*)d_in[12];
    const float* ffn1_b = (const float*)d_in[13];
    const float* ffn2_W = (const float*)d_in[14];
    const float* ffn2_b = (const float*)d_in[15];
    const float* dsc_W = (const float*)d_in[16];
    const float* dsc_b = (const float*)d_in[17];
    const float* dwav_W = (const float*)d_in[18];
    const float* dwav_b = (const float*)d_in[19];
    const float* dscl_W = (const float*)d_in[20];
    const float* dscl_b = (const float*)d_in[21];
    const int* length = (const int*)d_in[22];
    float* outp = (float*)d_out;

    float *p_eig, *p_x, *p_qkv, *p_o;
    cudaGetSymbolAddress((void**)&p_eig, g_eig);
    cudaGetSymbolAddress((void**)&p_x, g_x);
    cudaGetSymbolAddress((void**)&p_qkv, g_qkv);
    cudaGetSymbolAddress((void**)&p_o, g_o);

    cudaFuncSetAttribute(k_mma, cudaFuncAttributeMaxDynamicSharedMemorySize, SMEM_MMA);

    // encoder
    k_encode<<<BB * NN, HH>>>(eigenvalue, eigw_W, eigw_b);
    // fp16 B operand (independent of transformer path)
    k_prepB<<<8192, 256>>>(eigenvector);
    // MHA block
    k_ln<<<BB * NN, HH>>>(p_eig, p_x, ln1_g, ln1_b);
    k_dense<0, false><<<dim3(6, 128), 256>>>(p_x, qkv_W, qkv_b, nullptr, p_qkv, 3 * HH);
    k_scores<<<dim3(16, 16, BB * NHD), 256>>>(length);
    k_softmax<<<BB * NHD * NN, 256>>>();
    k_av<<<dim3(16, BB * NHD), 256>>>();
    k_dense<0, true><<<dim3(2, 128), 256>>>(p_o, out_W, out_b, p_eig, p_eig, HH);
    // FFN block
    k_ln<<<BB * NN, HH>>>(p_eig, p_x, ln2_g, ln2_b);
    k_dense<1, false><<<dim3(2, 128), 256>>>(p_x, ffn1_W, ffn1_b, nullptr, p_qkv, HH);
    k_dense<0, true><<<dim3(2, 128), 256>>>(p_qkv, ffn2_W, ffn2_b, p_eig, p_eig, HH);
    // decoders
    k_rowsum<<<BB, 512>>>(length);
    k_decode<<<BB, 128>>>(length, dsc_W, dsc_b, dwav_W, dwav_b, dscl_W, dscl_b);
    // spectral weights + fp16 hi/lo A operands
    k_fsa<<<dim3(4, BB), 256>>>(eigenvalue);
    k_prepAs<<<8192, 256>>>(eigenvector);
    // HMMA filter GEMM (symmetric: 36 tile pairs)
    k_mma<<<dim3(36, 40), 256, SMEM_MMA>>>(outp);
    // normalize columns
    k_normp<<<dim3(4, 5 * BB, 8), 256>>>(outp);
    k_normc<<<160, 256>>>();
    k_div<<<40960, 256>>>(outp);
}